// round 16
// baseline (speedup 1.0000x reference)
#include <cuda_runtime.h>
#include <cuda_bf16.h>

// Problem constants (fixed by reference)
#define BN    4096
#define NTOTN 100000
#define DN    32
#define HN    64
#define TN    8
#define NEGV  (-1e9f)

// One warp per batch element, 4 warps/block, 7 blocks/SM -> whole grid resident
// in a single wave. Fully independent warps.
// Lane layout: q = lane&15 (chunk), hh = lane>>4 (row parity); myrow = 2q+hh.
// Keys gather split: rows 0..15 via cp.async->smem (no registers), rows 16..31
// via an 8xfloat4 register buffer. Wh-hoist + LN execute INSIDE the DRAM
// latency window (loads issued first, folds deferred).
__global__ __launch_bounds__(128, 7)
void gfn_rollout_kernel(const float* __restrict__ qt,         // [B,64]
                        const int*   __restrict__ nbr,        // [NTOT,32]
                        const int*   __restrict__ start,      // [B]
                        const void*  __restrict__ evp,        // [NTOT,32] bool (dtype detected)
                        const float* __restrict__ keys,       // [NTOT,32,64]
                        const float* __restrict__ Wi,         // [64,64]
                        const float* __restrict__ Wh,         // [64,64]
                        const float* __restrict__ Wk,         // [64,64]
                        const float* __restrict__ g,          // [66]
                        const float* __restrict__ be,         // [66]
                        const float* __restrict__ sw,         // [66]
                        const float* __restrict__ sbp,        // [1]
                        const float* __restrict__ temp,       // [1]
                        float* __restrict__ out)
{
    __shared__ float shid[4][HN];                    // hidden per warp
    __shared__ float ssel[4][HN];                    // selected key row per warp
    __shared__ __align__(16) float4 skey[4][8 * 32]; // rows 0..15 staging (4KB/warp)

    const int w     = threadIdx.x >> 5;
    const int lane  = threadIdx.x & 31;
    const int q     = lane & 15;
    const int hh    = lane >> 4;
    const int myrow = 2 * q + hh;
    const int b     = blockIdx.x * 4 + w;

    float*  sh  = shid[w];
    float*  ss  = ssel[w];
    float4* sk4 = skey[w];

    const float tclamp = fmaxf(temp[0], 1e-5f);
    const float itc    = 1.0f / tclamp;
    const float stop_b = sbp[0];

    // ---- detect edge_valid element width (word-typed int32/float32 vs byte bool) ----
    bool word_typed;
    {
        const unsigned* wv = (const unsigned*)evp;
        bool ok = true;
        #pragma unroll
        for (int i = 0; i < 4; i++) {
            unsigned v = wv[i * 32 + lane];
            ok &= (v == 0u || v == 1u || v == 0x3F800000u);
        }
        word_typed = __all_sync(0xffffffffu, ok);
    }
    const unsigned*      ev32 = (const unsigned*)evp;
    const unsigned char* ev8  = (const unsigned char*)evp;

    int curr = start[b];

    // ---- carried loads for the first node (row = lane) ----
    int nb   = __ldg(&nbr[(size_t)curr * DN + lane]);
    int vraw = word_typed ? (ev32[(size_t)curr * DN + lane] != 0u)
                          : (ev8 [(size_t)curr * DN + lane] != 0);

    // ---- fold LN constants: ((c*rstd)*g+be)*sw == rstd*(Sg - mu*Gsum) + bsum ----
    const float gsw0 = __ldg(&g[lane])      * __ldg(&sw[lane]);
    const float gsw1 = __ldg(&g[lane + 32]) * __ldg(&sw[lane + 32]);
    float gsw64 = 0.f, gsw65 = 0.f;
    float bsum, Gsum;
    {
        float bs = __ldg(&be[lane]) * __ldg(&sw[lane])
                 + __ldg(&be[lane + 32]) * __ldg(&sw[lane + 32]);
        float gs = gsw0 + gsw1;
        if (lane == 0) {
            gsw64 = __ldg(&g[64]) * __ldg(&sw[64]);
            gsw65 = __ldg(&g[65]) * __ldg(&sw[65]);
            bs += __ldg(&be[64]) * __ldg(&sw[64]) + __ldg(&be[65]) * __ldg(&sw[65]);
            gs += gsw64 + gsw65;
        }
        #pragma unroll
        for (int o = 16; o; o >>= 1) {
            bs += __shfl_xor_sync(~0u, bs, o);
            gs += __shfl_xor_sync(~0u, gs, o);
        }
        bsum = bs; Gsum = gs;
    }

    // ---- init hidden = tanh(q[b] @ W_init), cooperative row-major matvec ----
    sh[lane]      = qt[b * HN + lane];
    sh[lane + 32] = qt[b * HN + lane + 32];
    __syncwarp();
    {
        float4 acc = make_float4(0.f, 0.f, 0.f, 0.f);
        #pragma unroll
        for (int it = 0; it < 32; it++) {
            int i = 2 * it + hh;
            float hv = sh[i];
            float4 wv = __ldg((const float4*)(Wi + i * HN + 4 * q));
            acc.x += hv * wv.x; acc.y += hv * wv.y;
            acc.z += hv * wv.z; acc.w += hv * wv.w;
        }
        acc.x += __shfl_xor_sync(0xffffffffu, acc.x, 16);
        acc.y += __shfl_xor_sync(0xffffffffu, acc.y, 16);
        acc.z += __shfl_xor_sync(0xffffffffu, acc.z, 16);
        acc.w += __shfl_xor_sync(0xffffffffu, acc.w, 16);
        __syncwarp();
        if (hh == 0) {
            float4 t4 = make_float4(tanhf(acc.x), tanhf(acc.y), tanhf(acc.z), tanhf(acc.w));
            *(float4*)(sh + 4 * q) = t4;
        }
        __syncwarp();
    }

    float lp_total = 0.f;
    int   nmoves   = 0;

    // output sections (float32, concatenated reference outputs)
    float* outA   = out;                          // actions_seq  [B,9]
    float* outTot = out + BN * 9;                 // log_pf_total [B]
    float* outS   = out + BN * 9 + BN;            // log_pf_steps [B,9]
    float* outNM  = out + BN * 9 + BN + BN * 9;   // num_moves    [B]

    int t = 0;
    for (t = 0; t <= TN; t++) {
        const float4* kb4 = (const float4*)(keys + (size_t)curr * (DN * HN));

        // ---- row-validity mask (bit r = edge r valid), horizon-masked ----
        unsigned vm = __ballot_sync(0xffffffffu, vraw);
        if (t >= TN) vm = 0u;
        int   vd       = (vm >> myrow) & 1;
        float has_edge = vm ? 1.f : 0.f;

        // ---- A: issue cp.async for rows 0..15 (smem, no regs), unpredicated ----
        #pragma unroll
        for (int j = 0; j < 8; j++) {
            unsigned dst = (unsigned)__cvta_generic_to_shared(&sk4[j * 32 + lane]);
            asm volatile("cp.async.ca.shared.global [%0], [%1], 16;"
                         :: "r"(dst), "l"(&kb4[j * 32 + lane]) : "memory");
        }
        asm volatile("cp.async.commit_group;" ::: "memory");

        // ---- B: issue predicated LDGs for rows 16..31 into register buffer ----
        float4 vbuf[8];
        #pragma unroll
        for (int j = 8; j < 16; j++) {
            vbuf[j - 8] = make_float4(0.f, 0.f, 0.f, 0.f);
            if ((vm >> (2 * j + hh)) & 1)
                vbuf[j - 8] = __ldg(&kb4[j * 32 + lane]);
        }

        // ---- C: Wh hoist matvec (L1-hit; fills the keys DRAM latency window) ----
        float4 acch = make_float4(0.f, 0.f, 0.f, 0.f);
        #pragma unroll
        for (int it = 0; it < 32; it++) {
            int i = 2 * it + hh;
            float hv = sh[i];
            float4 wh4 = __ldg((const float4*)(Wh + i * HN + 4 * q));
            acch.x += hv * wh4.x; acch.y += hv * wh4.y;
            acch.z += hv * wh4.z; acch.w += hv * wh4.w;
        }

        // ---- D: fused single-pass LN (independent of keys) ----
        float x0 = sh[lane], x1 = sh[lane + 32];
        float e64 = (float)t / (float)TN;
        float e65 = has_edge;
        float s1 = x0 + x1;
        float s2 = x0 * x0 + x1 * x1;
        float sg = x0 * gsw0 + x1 * gsw1;
        if (lane == 0) {
            s1 += e64 + e65;
            s2 += e64 * e64 + e65 * e65;
            sg += e64 * gsw64 + e65 * gsw65;
        }
        #pragma unroll
        for (int o = 16; o; o >>= 1) {
            s1 += __shfl_xor_sync(~0u, s1, o);
            s2 += __shfl_xor_sync(~0u, s2, o);
            sg += __shfl_xor_sync(~0u, sg, o);
        }
        float mu = s1 * (1.f / 66.f);
        float var = s2 * (1.f / 66.f) - mu * mu;
        float rstd = rsqrtf(var + 1e-5f);
        float stop_logit = ((sg - mu * Gsum) * rstd + bsum + stop_b) * itc;

        // ---- E: fold register half -> p[8..15] ----
        float4 h4 = *(const float4*)(sh + 4 * q);
        float p[16];
        #pragma unroll
        for (int j = 8; j < 16; j++) {
            float4 v = vbuf[j - 8];
            p[j] = v.x * h4.x + v.y * h4.y + v.z * h4.z + v.w * h4.w;
        }

        // ---- F/G: wait for cp.async, fold smem half -> p[0..7] (own-thread data) ----
        asm volatile("cp.async.wait_group 0;" ::: "memory");
        #pragma unroll
        for (int j = 0; j < 8; j++) {
            float4 v = sk4[j * 32 + lane];
            float d = v.x * h4.x + v.y * h4.y + v.z * h4.z + v.w * h4.w;
            p[j] = ((vm >> (2 * j + hh)) & 1) ? d : 0.f;
        }

        // ---- H: transpose-reduce over chunks (within each 16-lane half) ----
        #pragma unroll
        for (int k = 8; k >= 1; k >>= 1) {
            bool hi = (q & k) != 0;
            #pragma unroll
            for (int i = 0; i < 8; i++) {
                if (i < k) {
                    float send = hi ? p[i] : p[i + k];
                    float recv = __shfl_xor_sync(0xffffffffu, send, k);
                    p[i] = (hi ? p[i + k] : p[i]) + recv;
                }
            }
        }
        float sc = p[0];
        float logit = (vd ? sc : NEGV) * itc;

        // ---- I: fused argmax + exp-sum (reference c = stop_logit; exact identity) ----
        float e  = __expf(logit - stop_logit);    // 0 for NEG-masked lanes
        float bv = logit; int bi = myrow; float es = e;
        #pragma unroll
        for (int o = 16; o; o >>= 1) {
            float ov  = __shfl_xor_sync(~0u, bv, o);
            int   oi  = __shfl_xor_sync(~0u, bi, o);
            float oes = __shfl_xor_sync(~0u, es, o);
            es += oes;
            if (ov > bv || (ov == bv && oi < bi)) { bv = ov; bi = oi; }
        }
        int action; float chosen;
        if (stop_logit > bv) { action = DN; chosen = stop_logit; }
        else                 { action = bi; chosen = bv; }
        float lp = chosen - (stop_logit + __logf(es + 1.0f));

        bool chose_stop = (action == DN);
        int  a = chose_stop ? (DN - 1) : action;
        int  act_rec = chose_stop ? -1 : curr * DN + a;

        if (lane == 0) {
            outA[b * 9 + t] = (float)act_rec;
            outS[b * 9 + t] = lp;
        }
        lp_total += lp;
        if (chose_stop) break;
        nmoves++;

        // ---- tail + carried loads for the NEXT node (hidden under Wk matvec) ----
        int tail = __shfl_sync(0xffffffffu, nb, a);
        int nb_n   = __ldg(&nbr[(size_t)tail * DN + lane]);
        int vraw_n = word_typed ? (ev32[(size_t)tail * DN + lane] != 0u)
                                : (ev8 [(size_t)tail * DN + lane] != 0);

        // ---- advance: finish with sel @ Wk half ----
        float4 selv = __ldg(&kb4[a * 16 + q]);    // chosen row line is in L1 (LDG or cp.async.ca)
        if (hh == 0) *(float4*)(ss + 4 * q) = selv;
        __syncwarp();

        float4 acc = acch;
        #pragma unroll
        for (int it = 0; it < 32; it++) {
            int i = 2 * it + hh;
            float sv = ss[i];
            float4 wk4 = __ldg((const float4*)(Wk + i * HN + 4 * q));
            acc.x += sv * wk4.x; acc.y += sv * wk4.y;
            acc.z += sv * wk4.z; acc.w += sv * wk4.w;
        }
        acc.x += __shfl_xor_sync(0xffffffffu, acc.x, 16);
        acc.y += __shfl_xor_sync(0xffffffffu, acc.y, 16);
        acc.z += __shfl_xor_sync(0xffffffffu, acc.z, 16);
        acc.w += __shfl_xor_sync(0xffffffffu, acc.w, 16);
        __syncwarp();
        if (hh == 0) {
            float4 t4 = make_float4(tanhf(acc.x), tanhf(acc.y), tanhf(acc.z), tanhf(acc.w));
            *(float4*)(sh + 4 * q) = t4;
        }
        __syncwarp();

        curr = tail;
        nb   = nb_n;
        vraw = vraw_n;
    }

    // ---- fill forced-stopped tail steps + totals ----
    if (lane == 0) {
        for (int tt = t + 1; tt <= TN; tt++) {
            outA[b * 9 + tt] = -1.f;
            outS[b * 9 + tt] = 0.f;
        }
        outTot[b] = lp_total;
        outNM[b]  = (float)nmoves;
    }
}

extern "C" void kernel_launch(void* const* d_in, const int* in_sizes, int n_in,
                              void* d_out, int out_size)
{
    const float* q     = (const float*)d_in[0];
    const int*   nbr   = (const int*)d_in[1];
    const int*   start = (const int*)d_in[2];
    const void*  ev    = (const void*)d_in[3];
    const float* keys  = (const float*)d_in[4];
    const float* Wi    = (const float*)d_in[5];
    const float* Wh    = (const float*)d_in[6];
    const float* Wk    = (const float*)d_in[7];
    const float* g     = (const float*)d_in[8];
    const float* be    = (const float*)d_in[9];
    const float* sw    = (const float*)d_in[10];
    const float* sb    = (const float*)d_in[11];
    const float* temp  = (const float*)d_in[12];
    float* out = (float*)d_out;

    gfn_rollout_kernel<<<BN / 4, 128>>>(q, nbr, start, ev, keys,
                                        Wi, Wh, Wk, g, be, sw, sb, temp, out);
}

// round 17
// speedup vs baseline: 1.1237x; 1.1237x over previous
#include <cuda_runtime.h>
#include <cuda_bf16.h>

// Problem constants (fixed by reference)
#define BN    4096
#define NTOTN 100000
#define DN    32
#define HN    64
#define TN    8
#define NEGV  (-1e9f)

// One warp per batch element, 4 warps/block, 7 blocks/SM -> whole grid resident
// in a single wave. Fully independent warps (no cross-element coupling).
// Lane layout: q = lane&15 (chunk), hh = lane>>4 (row parity); myrow = 2q+hh.
// ev/nbr rows for the NEXT node are loaded as soon as the tail is known
// (carried registers), so the validity mask is ready BEFORE the keys gather,
// enabling a predicated gather that skips invalid rows (~50% of key traffic).
__global__ __launch_bounds__(128, 7)
void gfn_rollout_kernel(const float* __restrict__ qt,         // [B,64]
                        const int*   __restrict__ nbr,        // [NTOT,32]
                        const int*   __restrict__ start,      // [B]
                        const void*  __restrict__ evp,        // [NTOT,32] bool (dtype detected)
                        const float* __restrict__ keys,       // [NTOT,32,64]
                        const float* __restrict__ Wi,         // [64,64]
                        const float* __restrict__ Wh,         // [64,64]
                        const float* __restrict__ Wk,         // [64,64]
                        const float* __restrict__ g,          // [66]
                        const float* __restrict__ be,         // [66]
                        const float* __restrict__ sw,         // [66]
                        const float* __restrict__ sbp,        // [1]
                        const float* __restrict__ temp,       // [1]
                        float* __restrict__ out)
{
    __shared__ float shid[4][HN];   // hidden per warp
    __shared__ float ssel[4][HN];   // selected key row per warp

    const int w     = threadIdx.x >> 5;
    const int lane  = threadIdx.x & 31;
    const int q     = lane & 15;
    const int hh    = lane >> 4;
    const int myrow = 2 * q + hh;
    const int b     = blockIdx.x * 4 + w;

    float* sh = shid[w];
    float* ss = ssel[w];

    const float tclamp = fmaxf(temp[0], 1e-5f);
    const float itc    = 1.0f / tclamp;
    const float stop_b = sbp[0];

    // ---- detect edge_valid element width (word-typed int32/float32 vs byte bool) ----
    bool word_typed;
    {
        const unsigned* wv = (const unsigned*)evp;
        bool ok = true;
        #pragma unroll
        for (int i = 0; i < 4; i++) {
            unsigned v = wv[i * 32 + lane];
            ok &= (v == 0u || v == 1u || v == 0x3F800000u);
        }
        word_typed = __all_sync(0xffffffffu, ok);
    }
    const unsigned*      ev32 = (const unsigned*)evp;
    const unsigned char* ev8  = (const unsigned char*)evp;

    int curr = start[b];

    // ---- carried loads for the first node (row = lane) ----
    int nb   = __ldg(&nbr[(size_t)curr * DN + lane]);
    int vraw = word_typed ? (ev32[(size_t)curr * DN + lane] != 0u)
                          : (ev8 [(size_t)curr * DN + lane] != 0);

    // ---- fold LN constants: ((c*rstd)*g+be)*sw == rstd*(Sg - mu*Gsum) + bsum ----
    const float gsw0 = __ldg(&g[lane])      * __ldg(&sw[lane]);
    const float gsw1 = __ldg(&g[lane + 32]) * __ldg(&sw[lane + 32]);
    float gsw64 = 0.f, gsw65 = 0.f;
    float bsum, Gsum;
    {
        float bs = __ldg(&be[lane]) * __ldg(&sw[lane])
                 + __ldg(&be[lane + 32]) * __ldg(&sw[lane + 32]);
        float gs = gsw0 + gsw1;
        if (lane == 0) {
            gsw64 = __ldg(&g[64]) * __ldg(&sw[64]);
            gsw65 = __ldg(&g[65]) * __ldg(&sw[65]);
            bs += __ldg(&be[64]) * __ldg(&sw[64]) + __ldg(&be[65]) * __ldg(&sw[65]);
            gs += gsw64 + gsw65;
        }
        #pragma unroll
        for (int o = 16; o; o >>= 1) {
            bs += __shfl_xor_sync(~0u, bs, o);
            gs += __shfl_xor_sync(~0u, gs, o);
        }
        bsum = bs; Gsum = gs;
    }

    // ---- init hidden = tanh(q[b] @ W_init), cooperative row-major matvec ----
    sh[lane]      = qt[b * HN + lane];
    sh[lane + 32] = qt[b * HN + lane + 32];
    __syncwarp();
    {
        float4 acc = make_float4(0.f, 0.f, 0.f, 0.f);
        #pragma unroll
        for (int it = 0; it < 32; it++) {
            int i = 2 * it + hh;
            float hv = sh[i];
            float4 wv = __ldg((const float4*)(Wi + i * HN + 4 * q));
            acc.x += hv * wv.x; acc.y += hv * wv.y;
            acc.z += hv * wv.z; acc.w += hv * wv.w;
        }
        acc.x += __shfl_xor_sync(0xffffffffu, acc.x, 16);
        acc.y += __shfl_xor_sync(0xffffffffu, acc.y, 16);
        acc.z += __shfl_xor_sync(0xffffffffu, acc.z, 16);
        acc.w += __shfl_xor_sync(0xffffffffu, acc.w, 16);
        __syncwarp();
        if (hh == 0) {
            float4 t4 = make_float4(tanhf(acc.x), tanhf(acc.y), tanhf(acc.z), tanhf(acc.w));
            *(float4*)(sh + 4 * q) = t4;
        }
        __syncwarp();
    }

    float lp_total = 0.f;
    int   nmoves   = 0;

    // output sections (float32, concatenated reference outputs)
    float* outA   = out;                          // actions_seq  [B,9]
    float* outTot = out + BN * 9;                 // log_pf_total [B]
    float* outS   = out + BN * 9 + BN;            // log_pf_steps [B,9]
    float* outNM  = out + BN * 9 + BN + BN * 9;   // num_moves    [B]

    int t = 0;
    for (t = 0; t <= TN; t++) {
        const float4* kb4 = (const float4*)(keys + (size_t)curr * (DN * HN));

        // ---- row-validity mask (bit r = edge r valid), horizon-masked ----
        unsigned vm = __ballot_sync(0xffffffffu, vraw);
        if (t >= TN) vm = 0u;
        int   vd       = (vm >> myrow) & 1;
        float has_edge = vm ? 1.f : 0.f;

        // ---- PREDICATED gather + partial dots: skip invalid rows entirely ----
        float4 h4 = *(const float4*)(sh + 4 * q);
        float p[16];
        #pragma unroll
        for (int it = 0; it < 16; it++) {
            p[it] = 0.f;
            if ((vm >> (2 * it + hh)) & 1) {
                float4 v = __ldg(&kb4[it * 32 + lane]);
                p[it] = v.x * h4.x + v.y * h4.y + v.z * h4.z + v.w * h4.w;
            }
        }

        // ---- transpose-reduce over chunks (within each 16-lane half) ----
        #pragma unroll
        for (int k = 8; k >= 1; k >>= 1) {
            bool hi = (q & k) != 0;
            #pragma unroll
            for (int i = 0; i < 8; i++) {
                if (i < k) {
                    float send = hi ? p[i] : p[i + k];
                    float recv = __shfl_xor_sync(0xffffffffu, send, k);
                    p[i] = (hi ? p[i + k] : p[i]) + recv;
                }
            }
        }
        float sc = p[0];

        // ---- HOISTED h @ Wh half-matvec (skip on forced-stop horizon step) ----
        float4 acch = make_float4(0.f, 0.f, 0.f, 0.f);
        if (t < TN) {
            #pragma unroll
            for (int it = 0; it < 32; it++) {
                int i = 2 * it + hh;
                float hv = sh[i];
                float4 wh4 = __ldg((const float4*)(Wh + i * HN + 4 * q));
                acch.x += hv * wh4.x; acch.y += hv * wh4.y;
                acch.z += hv * wh4.z; acch.w += hv * wh4.w;
            }
        }

        float logit = (vd ? sc : NEGV) * itc;

        // ---- fused single-pass LN (S1, S2, Sg reduced together) ----
        float x0 = sh[lane], x1 = sh[lane + 32];
        float e64 = (float)t / (float)TN;
        float e65 = has_edge;
        float s1 = x0 + x1;
        float s2 = x0 * x0 + x1 * x1;
        float sg = x0 * gsw0 + x1 * gsw1;
        if (lane == 0) {
            s1 += e64 + e65;
            s2 += e64 * e64 + e65 * e65;
            sg += e64 * gsw64 + e65 * gsw65;
        }
        #pragma unroll
        for (int o = 16; o; o >>= 1) {
            s1 += __shfl_xor_sync(~0u, s1, o);
            s2 += __shfl_xor_sync(~0u, s2, o);
            sg += __shfl_xor_sync(~0u, sg, o);
        }
        float mu = s1 * (1.f / 66.f);
        float var = s2 * (1.f / 66.f) - mu * mu;
        float rstd = rsqrtf(var + 1e-5f);
        float stop_logit = ((sg - mu * Gsum) * rstd + bsum + stop_b) * itc;

        // ---- fused argmax + exp-sum (reference c = stop_logit; exact identity) ----
        float e  = __expf(logit - stop_logit);    // 0 for NEG-masked lanes
        float bv = logit; int bi = myrow; float es = e;
        #pragma unroll
        for (int o = 16; o; o >>= 1) {
            float ov  = __shfl_xor_sync(~0u, bv, o);
            int   oi  = __shfl_xor_sync(~0u, bi, o);
            float oes = __shfl_xor_sync(~0u, es, o);
            es += oes;
            if (ov > bv || (ov == bv && oi < bi)) { bv = ov; bi = oi; }
        }
        int action; float chosen;
        if (stop_logit > bv) { action = DN; chosen = stop_logit; }
        else                 { action = bi; chosen = bv; }
        float lp = chosen - (stop_logit + __logf(es + 1.0f));

        bool chose_stop = (action == DN);
        int  a = chose_stop ? (DN - 1) : action;
        int  act_rec = chose_stop ? -1 : curr * DN + a;

        if (lane == 0) {
            outA[b * 9 + t] = (float)act_rec;
            outS[b * 9 + t] = lp;
        }
        lp_total += lp;
        if (chose_stop) break;
        nmoves++;

        // ---- tail + carried loads for the NEXT node (hidden under Wk matvec) ----
        int tail = __shfl_sync(0xffffffffu, nb, a);
        int nb_n   = __ldg(&nbr[(size_t)tail * DN + lane]);
        int vraw_n = word_typed ? (ev32[(size_t)tail * DN + lane] != 0u)
                                : (ev8 [(size_t)tail * DN + lane] != 0);

        // ---- advance: finish with sel @ Wk half ----
        float4 selv = __ldg(&kb4[a * 16 + q]);    // chosen row (fetched in gather -> L1)
        if (hh == 0) *(float4*)(ss + 4 * q) = selv;
        __syncwarp();

        float4 acc = acch;
        #pragma unroll
        for (int it = 0; it < 32; it++) {
            int i = 2 * it + hh;
            float sv = ss[i];
            float4 wk4 = __ldg((const float4*)(Wk + i * HN + 4 * q));
            acc.x += sv * wk4.x; acc.y += sv * wk4.y;
            acc.z += sv * wk4.z; acc.w += sv * wk4.w;
        }
        acc.x += __shfl_xor_sync(0xffffffffu, acc.x, 16);
        acc.y += __shfl_xor_sync(0xffffffffu, acc.y, 16);
        acc.z += __shfl_xor_sync(0xffffffffu, acc.z, 16);
        acc.w += __shfl_xor_sync(0xffffffffu, acc.w, 16);
        __syncwarp();
        if (hh == 0) {
            float4 t4 = make_float4(tanhf(acc.x), tanhf(acc.y), tanhf(acc.z), tanhf(acc.w));
            *(float4*)(sh + 4 * q) = t4;
        }
        __syncwarp();

        curr = tail;
        nb   = nb_n;
        vraw = vraw_n;
    }

    // ---- fill forced-stopped tail steps + totals ----
    if (lane == 0) {
        for (int tt = t + 1; tt <= TN; tt++) {
            outA[b * 9 + tt] = -1.f;
            outS[b * 9 + tt] = 0.f;
        }
        outTot[b] = lp_total;
        outNM[b]  = (float)nmoves;
    }
}

extern "C" void kernel_launch(void* const* d_in, const int* in_sizes, int n_in,
                              void* d_out, int out_size)
{
    const float* q     = (const float*)d_in[0];
    const int*   nbr   = (const int*)d_in[1];
    const int*   start = (const int*)d_in[2];
    const void*  ev    = (const void*)d_in[3];
    const float* keys  = (const float*)d_in[4];
    const float* Wi    = (const float*)d_in[5];
    const float* Wh    = (const float*)d_in[6];
    const float* Wk    = (const float*)d_in[7];
    const float* g     = (const float*)d_in[8];
    const float* be    = (const float*)d_in[9];
    const float* sw    = (const float*)d_in[10];
    const float* sb    = (const float*)d_in[11];
    const float* temp  = (const float*)d_in[12];
    float* out = (float*)d_out;

    gfn_rollout_kernel<<<BN / 4, 128>>>(q, nbr, start, ev, keys,
                                        Wi, Wh, Wk, g, be, sw, sb, temp, out);
}